// round 17
// baseline (speedup 1.0000x reference)
#include <cuda_runtime.h>
#include <cuda_bf16.h>

// yolo_detect_target: out = sum_{i < cutoff} ( max(post_result[i,:]) + sum(boxes[i,:]) )
// cutoff = first row whose max-score < CONF (cumprod prefix-mask semantics).
//
// R9 structure (98.8us @ 86.8% DRAM) + single change: score loop unrolled x2
// with TWO fixed staging buffers (loop-invariant bases) -> one __syncwarp per
// group instead of two. (R12's regression is attributed to its per-iteration
// variable staging base; this variant tests that attribution.)
//
// Single fused kernel (grid 2368x256):
//   - box warps  (first 1/16 of warps): coalesced sum(boxes) over ALL rows
//   - score warps: FULL-WIDTH flat stream, 16 rows / group: each lane loads
//     10 contiguous float4 (512B/instr, MLP=10), max4 -> smem -> lanes 0..15
//     reduce one row each via 5x LDS.128; buffers alternate A/B per group.
//   - last block (ticket): exact fixup for rows >= cutoff + tail, writes out,
//     resets globals for next graph replay.
// NOTE: assumes scores nonnegative (inputs uniform [0,1)) for 0-init max trick.

#define CONF_THRESH 0.25f

__device__ float        g_total  = 0.0f;
__device__ int          g_cutoff = 0x7fffffff;
__device__ unsigned int g_done   = 0u;

__device__ __forceinline__ float max4(float4 t) {
    return fmaxf(fmaxf(t.x, t.y), fmaxf(t.z, t.w));
}

// One 16-row score group: load, stage, reduce, accumulate, cutoff-detect.
// WSM must be a loop-invariant (fixed) shared-memory base.
#define SCORE_GROUP(WSM)                                                      \
    {                                                                         \
        const int row0 = g << 4;                                              \
        const long long base = (long long)row0 * 20;                          \
        float4 t[10];                                                         \
        _Pragma("unroll")                                                     \
        for (int j = 0; j < 10; j++)                                          \
            t[j] = __ldcs(&pr4[base + j * 32 + lane]);  /* 512B, MLP=10 */    \
        _Pragma("unroll")                                                     \
        for (int j = 0; j < 10; j++)                                          \
            (WSM)[j * 32 + lane] = max4(t[j]);                                \
        __syncwarp();                                                         \
        float sc = 1.0f;                 /* >= CONF for inactive lanes */     \
        if (lane < 16) {                                                      \
            const float4* rp4 = (const float4*)((WSM) + lane * 20);           \
            float4 a0 = rp4[0], a1 = rp4[1], a2 = rp4[2],                     \
                   a3 = rp4[3], a4 = rp4[4];                                  \
            sc = fmaxf(fmaxf(fmaxf(max4(a0), max4(a1)),                       \
                             fmaxf(max4(a2), max4(a3))), max4(a4));           \
            acc += sc;                                                        \
        }                                                                     \
        unsigned bad = __ballot_sync(0xffffffffu, sc < CONF_THRESH);          \
        if (bad && lane == 0)                                                 \
            atomicMin(&g_cutoff, row0 + __ffs(bad) - 1);                      \
    }
    // No trailing syncwarp: the next group writes the OTHER buffer; this
    // buffer is only rewritten after an intervening __syncwarp (fence).

__global__ void __launch_bounds__(256, 6)
yolo_fused_kernel(const float4* __restrict__ pr4,
                  const float4* __restrict__ bx4,
                  int n, int c, float* __restrict__ out) {
    const int lane   = threadIdx.x & 31;
    const int wid    = threadIdx.x >> 5;     // warp in block (0..7)
    const int gwarp  = (int)((blockIdx.x * blockDim.x + threadIdx.x) >> 5);
    const int nwarps = (int)((gridDim.x * blockDim.x) >> 5);
    const int nv     = c >> 2;               // float4 per row (20 for C=80)
    const int nboxw  = nwarps >> 4;          // 1/16 of warps stream boxes

    __shared__ float ws [8][320];            // staging buffer A (fixed base)
    __shared__ float ws2[8][320];            // staging buffer B (fixed base)
    __shared__ float sh[256];

    float acc = 0.0f;

    if (gwarp < nboxw) {
        // Pure coalesced box stream over ALL rows.
        const int tid = gwarp * 32 + lane;
        const int nth = nboxw * 32;
        for (int i = tid; i < n; i += nth) {
            float4 bb = __ldcs(&bx4[i]);
            acc += (bb.x + bb.y) + (bb.z + bb.w);
        }
    } else if (nv == 20) {
        // Score stream, specialized C=80; unrolled x2 over alternating buffers.
        const int sw   = gwarp - nboxw;
        const int nsw  = nwarps - nboxw;
        const int ngrp = n >> 4;             // 16-row groups
        float* wsmA = ws[wid];
        float* wsmB = ws2[wid];

        int g = sw;
        while (g < ngrp) {
            SCORE_GROUP(wsmA);
            g += nsw;
            if (g >= ngrp) break;
            SCORE_GROUP(wsmB);
            g += nsw;
        }
    } else {
        // Generic fallback (not hit for C=80): 8 rows/warp, lanes 0..nv-1.
        const int sw   = gwarp - nboxw;
        const int nsw  = nwarps - nboxw;
        const int ngrp = n >> 3;
        for (int g = sw; g < ngrp; g += nsw) {
            const int row0 = g << 3;
            const long long b = (long long)row0 * nv;
            float m[8];
            #pragma unroll
            for (int k = 0; k < 8; k++) m[k] = 0.0f;
            if (lane < nv) {
                #pragma unroll
                for (int k = 0; k < 8; k++)
                    m[k] = max4(__ldcs(&pr4[b + (long long)k * nv + lane]));
            }
            #pragma unroll
            for (int k = 0; k < 8; k++) {
                float sc = __int_as_float(
                    __reduce_max_sync(0xffffffffu, __float_as_int(m[k])));
                if (lane == 0) {
                    acc += sc;
                    if (sc < CONF_THRESH) atomicMin(&g_cutoff, row0 + k);
                }
            }
        }
    }

    // Block reduction -> one atomicAdd per block.
    sh[threadIdx.x] = acc;
    __syncthreads();
    #pragma unroll
    for (int o = 128; o > 0; o >>= 1) {
        if (threadIdx.x < o) sh[threadIdx.x] += sh[threadIdx.x + o];
        __syncthreads();
    }

    __shared__ int s_last;
    if (threadIdx.x == 0) {
        atomicAdd(&g_total, sh[0]);
        __threadfence();  // make this block's total/cutoff visible before ticket
        unsigned int ticket = atomicAdd(&g_done, 1u);
        s_last = (ticket == gridDim.x - 1u) ? 1 : 0;
    }
    __syncthreads();
    if (!s_last) return;

    // ---- Last block only: fixup + output + reset ----
    const int ngrpT = (nv == 20) ? ((n >> 4) << 4) : ((n >> 3) << 3);

    __shared__ int s_cut;
    if (threadIdx.x == 0)
        s_cut = min(atomicMin(&g_cutoff, 0x7fffffff), n);  // atomic read
    __syncthreads();

    float adj = 0.0f;

    // Warp 0: tail rows [ngrpT, n) in order (may lower the cutoff).
    if (wid == 0) {
        int cut = s_cut;
        for (int row = ngrpT; row < n; row++) {
            if (row < cut) {
                float mm = 0.0f;
                for (int v = lane; v < nv; v += 32)
                    mm = fmaxf(mm, max4(pr4[(long long)row * nv + v]));
                float sc = __int_as_float(
                    __reduce_max_sync(0xffffffffu, __float_as_int(mm)));
                if (sc < CONF_THRESH) {
                    cut = row;                       // excluded: remove its boxsum
                    if (lane == 0) {
                        float4 bb = bx4[row];
                        adj -= (bb.x + bb.y) + (bb.z + bb.w);
                    }
                } else if (lane == 0) {
                    adj += sc;                       // boxsum already in g_total
                }
            } else if (lane == 0) {
                float4 bb = bx4[row];                // excluded tail row
                adj -= (bb.x + bb.y) + (bb.z + bb.w);
            }
        }
        if (lane == 0) s_cut = cut;
    }
    __syncthreads();
    const int cut = s_cut;

    // Subtract excluded group rows [cut, ngrpT): one row per warp, strided.
    for (int row = cut + wid; row < ngrpT; row += 8) {
        float mm = 0.0f;
        for (int v = lane; v < nv; v += 32)
            mm = fmaxf(mm, max4(pr4[(long long)row * nv + v]));
        float sc = __int_as_float(__reduce_max_sync(0xffffffffu, __float_as_int(mm)));
        if (lane == 0) {
            float4 bb = bx4[row];
            adj -= sc + ((bb.x + bb.y) + (bb.z + bb.w));
        }
    }

    sh[threadIdx.x] = adj;
    __syncthreads();
    #pragma unroll
    for (int o = 128; o > 0; o >>= 1) {
        if (threadIdx.x < o) sh[threadIdx.x] += sh[threadIdx.x + o];
        __syncthreads();
    }
    if (threadIdx.x == 0) {
        out[0] = atomicAdd(&g_total, 0.0f) + sh[0];
        g_total  = 0.0f;            // reset for next graph replay
        g_cutoff = 0x7fffffff;
        g_done   = 0u;
    }
}

extern "C" void kernel_launch(void* const* d_in, const int* in_sizes, int n_in,
                              void* d_out, int out_size) {
    const float* pr = (const float*)d_in[0];   // post_result [N, C] float32
    const float* bx = (const float*)d_in[1];   // pre_post_boxes [N, 4] float32
    const int nrows = in_sizes[1] / 4;
    const int c     = in_sizes[0] / nrows;     // 80

    yolo_fused_kernel<<<2368, 256>>>((const float4*)pr, (const float4*)bx,
                                     nrows, c, (float*)d_out);
}